// round 12
// baseline (speedup 1.0000x reference)
#include <cuda_runtime.h>
#include <cuda_fp16.h>
#include <math.h>

#define Bv 256
#define NT 197
#define CC 768
#define HH 12
#define DH 64
#define GRID 14
#define M_ROWS (Bv * NT)          // 50432 = 394*128

// ---------------- scratch ----------------
__device__ __half g_qh[(size_t)Bv * HH * NT * DH];
__device__ __half g_ql[(size_t)Bv * HH * NT * DH];
__device__ __half g_kh[(size_t)Bv * HH * NT * DH];
__device__ __half g_vh[(size_t)Bv * HH * NT * DH];
__device__ __half g_ah[(size_t)M_ROWS * CC];
__device__ __half g_al[(size_t)M_ROWS * CC];
__device__ __half g_xh[(size_t)M_ROWS * CC];
__device__ __half g_xl[(size_t)M_ROWS * CC];
__device__ __half g_wqh[(size_t)CC * 3 * CC];
__device__ __half g_wph[(size_t)CC * CC];

// ---------------- helpers ----------------
__device__ __forceinline__ unsigned smem_u32(const void* p) {
    return (unsigned)__cvta_generic_to_shared(p);
}
__device__ __forceinline__ void cp_async16_u(unsigned s, const void* g) {
    asm volatile("cp.async.cg.shared.global [%0], [%1], 16;\n" :: "r"(s), "l"(g));
}
__device__ __forceinline__ void ldsm_x4(unsigned& r0, unsigned& r1, unsigned& r2, unsigned& r3,
                                        unsigned addr) {
    asm volatile("ldmatrix.sync.aligned.m8n8.x4.shared.b16 {%0,%1,%2,%3}, [%4];\n"
                 : "=r"(r0), "=r"(r1), "=r"(r2), "=r"(r3) : "r"(addr));
}
__device__ __forceinline__ void ldsm_x4t(unsigned& r0, unsigned& r1, unsigned& r2, unsigned& r3,
                                         unsigned addr) {
    asm volatile("ldmatrix.sync.aligned.m8n8.x4.trans.shared.b16 {%0,%1,%2,%3}, [%4];\n"
                 : "=r"(r0), "=r"(r1), "=r"(r2), "=r"(r3) : "r"(addr));
}
__device__ __forceinline__ void ldsm_x2t(unsigned& r0, unsigned& r1, unsigned addr) {
    asm volatile("ldmatrix.sync.aligned.m8n8.x2.trans.shared.b16 {%0,%1}, [%2];\n"
                 : "=r"(r0), "=r"(r1) : "r"(addr));
}
__device__ __forceinline__ void mma16816h(float* c, unsigned a0, unsigned a1, unsigned a2,
                                          unsigned a3, unsigned b0, unsigned b1) {
    asm volatile("mma.sync.aligned.m16n8k16.row.col.f32.f16.f16.f32 "
                 "{%0,%1,%2,%3}, {%4,%5,%6,%7}, {%8,%9}, {%0,%1,%2,%3};\n"
                 : "+f"(c[0]), "+f"(c[1]), "+f"(c[2]), "+f"(c[3])
                 : "r"(a0), "r"(a1), "r"(a2), "r"(a3), "r"(b0), "r"(b1));
}
__device__ __forceinline__ void split_store4h(__half* hp, __half* lp, float4 v) {
    __half2 h0, h1, l0, l1;
    h0.x = __float2half_rn(v.x); l0.x = __float2half_rn(v.x - __half2float(h0.x));
    h0.y = __float2half_rn(v.y); l0.y = __float2half_rn(v.y - __half2float(h0.y));
    h1.x = __float2half_rn(v.z); l1.x = __float2half_rn(v.z - __half2float(h1.x));
    h1.y = __float2half_rn(v.w); l1.y = __float2half_rn(v.w - __half2float(h1.y));
    reinterpret_cast<__half2*>(hp)[0] = h0;
    reinterpret_cast<__half2*>(hp)[1] = h1;
    reinterpret_cast<__half2*>(lp)[0] = l0;
    reinterpret_cast<__half2*>(lp)[1] = l1;
}
__device__ __forceinline__ void split2h(float x, float y, __half2& h, __half2& l) {
    h.x = __float2half_rn(x); l.x = __float2half_rn(x - __half2float(h.x));
    h.y = __float2half_rn(y); l.y = __float2half_rn(y - __half2float(h.y));
}
__device__ __forceinline__ unsigned pack_hi_h(float x, float y) {
    __half2 t; t.x = __float2half_rn(x); t.y = __float2half_rn(y);
    return *reinterpret_cast<unsigned*>(&t);
}
__device__ __forceinline__ unsigned pack_lo_h(float x, float y) {
    __half hx = __float2half_rn(x);
    __half hy = __float2half_rn(y);
    __half2 t;
    t.x = __float2half_rn(x - __half2float(hx));
    t.y = __float2half_rn(y - __half2float(hy));
    return *reinterpret_cast<unsigned*>(&t);
}

// ---------------- convert kernels ----------------
__global__ __launch_bounds__(256)
void cvt_split_kernel(const float* __restrict__ src, __half* __restrict__ hi,
                      __half* __restrict__ lo)
{
    const int i = blockIdx.x * 256 + threadIdx.x;
    float4 v = reinterpret_cast<const float4*>(src)[i];
    split_store4h(hi + (size_t)i * 4, lo + (size_t)i * 4, v);
}
__global__ __launch_bounds__(256)
void cvt_hi_kernel(const float* __restrict__ src, __half* __restrict__ hi)
{
    const int i = blockIdx.x * 256 + threadIdx.x;
    float4 v = reinterpret_cast<const float4*>(src)[i];
    __half2 h0, h1;
    h0.x = __float2half_rn(v.x); h0.y = __float2half_rn(v.y);
    h1.x = __float2half_rn(v.z); h1.y = __float2half_rn(v.w);
    reinterpret_cast<__half2*>(hi + (size_t)i * 4)[0] = h0;
    reinterpret_cast<__half2*>(hi + (size_t)i * 4)[1] = h1;
}

// ---------------- fp16x2 GEMM: 128x128x32 CTA, 3-stage cp.async, single sync/iter ----------------
// A split hi/lo, B hi only. D = Ah*Bh + Al*Bh.
#define LDA 40    // 32 + 8 pad (fp16)
#define LDB 136   // 128 + 8 pad
#define GS_A_HL  (128 * LDA * 2)                 // 10240 B (one hl plane)
#define GS_A     (2 * GS_A_HL)                   // 20480 B
#define GS_B     (32 * LDB * 2)                  // 8704 B
#define GS_STAGE (GS_A + GS_B)                   // 29184 B
#define GS_TOTAL (3 * GS_STAGE)                  // 87552 B

template<int MODE>
__global__ __launch_bounds__(256, 2)
void mma_gemm_h(const __half* __restrict__ Agh, const __half* __restrict__ Agl,
                const __half* __restrict__ Bgh,
                const float* __restrict__ bias, float* __restrict__ C,
                __half* __restrict__ Qh, __half* __restrict__ Ql,
                __half* __restrict__ Kh, __half* __restrict__ Vh,
                int M, int N, int K)
{
    extern __shared__ char gsm[];
    const unsigned smBase = smem_u32(gsm);

    const int tid  = threadIdx.x;
    const int brow = blockIdx.y;
    const int bcol = blockIdx.x;
    const int lane = tid & 31;
    const int wid  = tid >> 5;
    const int wm = (wid & 1) * 64;
    const int wn = (wid >> 1) * 32;
    const int aRowBase = brow * 128;
    const int bColBase = bcol * 128;

    float acc[4][4][4];
    #pragma unroll
    for (int mt = 0; mt < 4; mt++)
        #pragma unroll
        for (int nt = 0; nt < 4; nt++)
            #pragma unroll
            for (int e = 0; e < 4; e++) acc[mt][nt][e] = 0.f;

    const int aRowLane = lane & 15;
    const int aColLane = (lane >> 4) << 3;
    const int bRowLane = lane & 15;

    auto issue = [&](int k0, int st) {
        const unsigned stBase = smBase + st * GS_STAGE;
        // A hi+lo: 1024 chunks of 16B (512 per plane; 4 chunks x 8 halves per row)
        #pragma unroll
        for (int c = 0; c < 4; c++) {
            const int chunk = tid + c * 256;          // 0..1023
            const int hl = chunk >> 9;
            const int rem = chunk & 511;
            const int arow = rem >> 2;
            const int acol = (rem & 3) << 3;
            const size_t aoff = (size_t)(aRowBase + arow) * K + k0 + acol;
            cp_async16_u(stBase + hl * GS_A_HL + (arow * LDA + acol) * 2,
                         (hl ? Agl : Agh) + aoff);
        }
        // B: 512 chunks of 16B (32 rows x 16 chunks)
        #pragma unroll
        for (int c = 0; c < 2; c++) {
            const int chunk = tid + c * 256;           // 0..511
            const int brw = chunk >> 4;
            const int bcl = (chunk & 15) << 3;
            const size_t boff = (size_t)(k0 + brw) * N + bColBase + bcl;
            cp_async16_u(stBase + GS_A + (brw * LDB + bcl) * 2, Bgh + boff);
        }
        asm volatile("cp.async.commit_group;\n");
    };

    const int NIT = K >> 5;
    issue(0, 0);
    issue(32, 1);

    int st = 0;
    for (int it = 0; it < NIT; ++it) {
        if (it + 1 < NIT) {
            asm volatile("cp.async.wait_group 1;\n");
        } else {
            asm volatile("cp.async.wait_group 0;\n");
        }
        __syncthreads();
        if (it + 2 < NIT) {
            int st2 = st + 2; if (st2 >= 3) st2 -= 3;
            issue((it + 2) << 5, st2);
        }

        const unsigned stBase = smBase + st * GS_STAGE;
        const unsigned aBaseH = stBase;
        const unsigned aBaseL = stBase + GS_A_HL;
        const unsigned bBaseH = stBase + GS_A;

        #pragma unroll
        for (int ks = 0; ks < 2; ks++) {
            unsigned bhf[4][2];
            #pragma unroll
            for (int nt = 0; nt < 4; nt++) {
                const unsigned boff = ((ks * 16 + bRowLane) * LDB + wn + nt * 8) * 2;
                ldsm_x2t(bhf[nt][0], bhf[nt][1], bBaseH + boff);
            }
            #pragma unroll
            for (int mt = 0; mt < 4; mt++) {
                const unsigned aoff = ((wm + mt * 16 + aRowLane) * LDA + ks * 16 + aColLane) * 2;
                unsigned ah0, ah1, ah2, ah3, al0, al1, al2, al3;
                ldsm_x4(ah0, ah1, ah2, ah3, aBaseH + aoff);
                ldsm_x4(al0, al1, al2, al3, aBaseL + aoff);
                #pragma unroll
                for (int nt = 0; nt < 4; nt++) {
                    mma16816h(acc[mt][nt], ah0, ah1, ah2, ah3, bhf[nt][0], bhf[nt][1]);
                    mma16816h(acc[mt][nt], al0, al1, al2, al3, bhf[nt][0], bhf[nt][1]);
                }
            }
        }
        if (++st >= 3) st -= 3;
    }

    const int trow = lane >> 2;
    const int tcol = (lane & 3) << 1;
    #pragma unroll
    for (int mt = 0; mt < 4; mt++) {
        #pragma unroll
        for (int nt = 0; nt < 4; nt++) {
            const int gc = bColBase + wn + nt * 8 + tcol;
            const float bia0 = bias[gc];
            const float bia1 = bias[gc + 1];
            #pragma unroll
            for (int half_ = 0; half_ < 2; half_++) {
                const int gr = aRowBase + wm + mt * 16 + trow + half_ * 8;
                float2 val;
                val.x = acc[mt][nt][half_ * 2 + 0] + bia0;
                val.y = acc[mt][nt][half_ * 2 + 1] + bia1;
                if (MODE == 0) {
                    *(float2*)&C[(size_t)gr * N + gc] = val;
                } else {
                    const int b_ = gr / NT;
                    const int t  = gr - b_ * NT;
                    const int s  = gc / CC;
                    const int r  = gc - s * CC;
                    const int hh = r >> 6;
                    const int d  = r & 63;
                    const size_t idx2 = (((size_t)((b_ * HH + hh) * NT + t)) * DH + d) >> 1;
                    if (s == 0) {
                        val.x *= 0.125f; val.y *= 0.125f;
                        __half2 h2, l2;
                        split2h(val.x, val.y, h2, l2);
                        reinterpret_cast<__half2*>(Qh)[idx2] = h2;
                        reinterpret_cast<__half2*>(Ql)[idx2] = l2;
                    } else {
                        __half2 h2;
                        h2.x = __float2half_rn(val.x);
                        h2.y = __float2half_rn(val.y);
                        reinterpret_cast<__half2*>((s == 1) ? Kh : Vh)[idx2] = h2;
                    }
                }
            }
        }
    }
}

// ---------------- fp16 tensor-core attention: one CTA per (b,h), 416 threads ----------------
#define ATT_ROWS 208
#define ATT_LD 72
#define ATT_ELEMS (ATT_ROWS * ATT_LD)   // 14976

__global__ __launch_bounds__(416, 1)
void attn_mma_kernel(const __half* __restrict__ qh, const __half* __restrict__ ql,
                     const __half* __restrict__ kh, const __half* __restrict__ vh,
                     __half* __restrict__ outh, __half* __restrict__ outl)
{
    extern __shared__ __half sm[];
    __half* smQH = sm;
    __half* smQL = sm + ATT_ELEMS;
    __half* smKH = sm + 2 * ATT_ELEMS;
    __half* smVH = sm + 3 * ATT_ELEMS;

    const int bh = blockIdx.x;
    const int b  = bh / HH;
    const int h  = bh - b * HH;
    const size_t base = (size_t)bh * NT * DH;
    const int tid  = threadIdx.x;
    const int lane = tid & 31;
    const int wid  = tid >> 5;     // 0..12

    const unsigned uQH = smem_u32(smQH);
    const unsigned uQL = smem_u32(smQL);
    const unsigned uKH = smem_u32(smKH);
    const unsigned uVH = smem_u32(smVH);

    for (int i = tid; i < NT * 8; i += 416) {      // 197 rows x 8 chunks
        const int row = i >> 3;
        const int j = i & 7;
        const unsigned doff = (unsigned)((row * ATT_LD + j * 8) * 2);
        const size_t soff = base + (size_t)row * DH + j * 8;
        cp_async16_u(uQH + doff, qh + soff);
        cp_async16_u(uQL + doff, ql + soff);
        cp_async16_u(uKH + doff, kh + soff);
        cp_async16_u(uVH + doff, vh + soff);
    }
    const float4 z4 = make_float4(0.f, 0.f, 0.f, 0.f);
    for (int i = tid; i < 11 * 8; i += 416) {
        const int row = NT + (i >> 3);
        const int j = i & 7;
        const int off = row * ATT_LD + j * 8;
        *(float4*)&smQH[off] = z4; *(float4*)&smQL[off] = z4;
        *(float4*)&smKH[off] = z4; *(float4*)&smVH[off] = z4;
    }
    asm volatile("cp.async.commit_group;\n");
    asm volatile("cp.async.wait_group 0;\n");
    __syncthreads();

    const int m0 = wid * 16;

    unsigned qf[4][4], qg[4][4];
    {
        const int r  = m0 + (lane & 15);
        const int cb = (lane >> 4) << 3;
        #pragma unroll
        for (int ks = 0; ks < 4; ks++) {
            const unsigned off = (unsigned)((r * ATT_LD + ks * 16 + cb) * 2);
            ldsm_x4(qf[ks][0], qf[ks][1], qf[ks][2], qf[ks][3], uQH + off);
            ldsm_x4(qg[ks][0], qg[ks][1], qg[ks][2], qg[ks][3], uQL + off);
        }
    }

    float s[25][4];
    #pragma unroll
    for (int nt = 0; nt < 25; nt++)
        #pragma unroll
        for (int e = 0; e < 4; e++) s[nt][e] = 0.f;

    const int krow = lane & 7;
    const int kcol = ((lane >> 3) & 3) << 3;
    #pragma unroll
    for (int nt = 0; nt < 25; nt++) {
        const int n0 = nt * 8;
        unsigned khf[4][2];
        {
            const unsigned o1 = (unsigned)(((n0 + krow) * ATT_LD + kcol) * 2);
            unsigned r0, r1, r2, r3;
            ldsm_x4(r0, r1, r2, r3, uKH + o1);
            khf[0][0] = r0; khf[0][1] = r1; khf[1][0] = r2; khf[1][1] = r3;
            ldsm_x4(r0, r1, r2, r3, uKH + o1 + 64);
            khf[2][0] = r0; khf[2][1] = r1; khf[3][0] = r2; khf[3][1] = r3;
        }
        #pragma unroll
        for (int ks = 0; ks < 4; ks++) {
            mma16816h(s[nt], qf[ks][0], qf[ks][1], qf[ks][2], qf[ks][3], khf[ks][0], khf[ks][1]);
            mma16816h(s[nt], qg[ks][0], qg[ks][1], qg[ks][2], qg[ks][3], khf[ks][0], khf[ks][1]);
        }
    }

    {
        const int col0 = 192 + ((lane & 3) << 1);
        if (col0     >= NT) { s[24][0] = -1e30f; s[24][2] = -1e30f; }
        if (col0 + 1 >= NT) { s[24][1] = -1e30f; s[24][3] = -1e30f; }
    }
    float mx0 = -1e30f, mx1 = -1e30f;
    #pragma unroll
    for (int nt = 0; nt < 25; nt++) {
        mx0 = fmaxf(mx0, fmaxf(s[nt][0], s[nt][1]));
        mx1 = fmaxf(mx1, fmaxf(s[nt][2], s[nt][3]));
    }
    mx0 = fmaxf(mx0, __shfl_xor_sync(0xffffffffu, mx0, 1));
    mx0 = fmaxf(mx0, __shfl_xor_sync(0xffffffffu, mx0, 2));
    mx1 = fmaxf(mx1, __shfl_xor_sync(0xffffffffu, mx1, 1));
    mx1 = fmaxf(mx1, __shfl_xor_sync(0xffffffffu, mx1, 2));

    float sum0 = 0.f, sum1 = 0.f;
    #pragma unroll
    for (int nt = 0; nt < 25; nt++) {
        const float e0 = __expf(s[nt][0] - mx0);
        const float e1 = __expf(s[nt][1] - mx0);
        const float e2 = __expf(s[nt][2] - mx1);
        const float e3 = __expf(s[nt][3] - mx1);
        s[nt][0] = e0; s[nt][1] = e1; s[nt][2] = e2; s[nt][3] = e3;
        sum0 += e0 + e1; sum1 += e2 + e3;
    }
    sum0 += __shfl_xor_sync(0xffffffffu, sum0, 1);
    sum0 += __shfl_xor_sync(0xffffffffu, sum0, 2);
    sum1 += __shfl_xor_sync(0xffffffffu, sum1, 1);
    sum1 += __shfl_xor_sync(0xffffffffu, sum1, 2);
    const float inv0 = 1.0f / sum0;
    const float inv1 = 1.0f / sum1;

    float o[8][4];
    #pragma unroll
    for (int nt = 0; nt < 8; nt++)
        #pragma unroll
        for (int e = 0; e < 4; e++) o[nt][e] = 0.f;

    const int vrow = ((lane >> 3) & 1) * 8 + (lane & 7);
    const int vcol = (lane >> 4) << 3;
    #pragma unroll
    for (int ks = 0; ks < 13; ks++) {
        unsigned ah0, ah1, ah2, ah3, al0, al1, al2, al3;
        if (ks < 12) {
            ah0 = pack_hi_h(s[2*ks][0],   s[2*ks][1]);   ah1 = pack_hi_h(s[2*ks][2],   s[2*ks][3]);
            ah2 = pack_hi_h(s[2*ks+1][0], s[2*ks+1][1]); ah3 = pack_hi_h(s[2*ks+1][2], s[2*ks+1][3]);
            al0 = pack_lo_h(s[2*ks][0],   s[2*ks][1]);   al1 = pack_lo_h(s[2*ks][2],   s[2*ks][3]);
            al2 = pack_lo_h(s[2*ks+1][0], s[2*ks+1][1]); al3 = pack_lo_h(s[2*ks+1][2], s[2*ks+1][3]);
        } else {
            ah0 = pack_hi_h(s[24][0], s[24][1]); ah1 = pack_hi_h(s[24][2], s[24][3]);
            al0 = pack_lo_h(s[24][0], s[24][1]); al1 = pack_lo_h(s[24][2], s[24][3]);
            ah2 = 0u; ah3 = 0u; al2 = 0u; al3 = 0u;
        }
        const int k0 = ks * 16;
        #pragma unroll
        for (int np = 0; np < 4; np++) {
            const unsigned off = (unsigned)(((k0 + vrow) * ATT_LD + np * 16 + vcol) * 2);
            unsigned vh0, vh1, vh2, vh3;
            ldsm_x4t(vh0, vh1, vh2, vh3, uVH + off);
            mma16816h(o[2 * np],     ah0, ah1, ah2, ah3, vh0, vh1);
            mma16816h(o[2 * np],     al0, al1, al2, al3, vh0, vh1);
            mma16816h(o[2 * np + 1], ah0, ah1, ah2, ah3, vh2, vh3);
            mma16816h(o[2 * np + 1], al0, al1, al2, al3, vh2, vh3);
        }
    }

    const int r0 = m0 + (lane >> 2);
    const int r1 = r0 + 8;
    const int cb = h * DH + ((lane & 3) << 1);
    if (r0 < NT) {
        const size_t ob = (((size_t)b * NT + r0) * CC + cb) >> 1;
        #pragma unroll
        for (int nt = 0; nt < 8; nt++) {
            __half2 h2, l2;
            split2h(o[nt][0] * inv0, o[nt][1] * inv0, h2, l2);
            reinterpret_cast<__half2*>(outh)[ob + nt * 4] = h2;
            reinterpret_cast<__half2*>(outl)[ob + nt * 4] = l2;
        }
    }
    if (r1 < NT) {
        const size_t ob = (((size_t)b * NT + r1) * CC + cb) >> 1;
        #pragma unroll
        for (int nt = 0; nt < 8; nt++) {
            __half2 h2, l2;
            split2h(o[nt][2] * inv1, o[nt][3] * inv1, h2, l2);
            reinterpret_cast<__half2*>(outh)[ob + nt * 4] = h2;
            reinterpret_cast<__half2*>(outl)[ob + nt * 4] = l2;
        }
    }
}

// ---------------- depthwise 3x3 conv on V (tokens 1:), residual add into hi/lo ----------------
__global__ __launch_bounds__(256)
void dwconv_kernel(const __half* __restrict__ vh,
                   const float* __restrict__ wgt, const float* __restrict__ bias,
                   __half* __restrict__ ah, __half* __restrict__ al)
{
    const int idx = blockIdx.x * 256 + threadIdx.x;
    const int c  = idx % CC;
    const int sp = (idx / CC) % (GRID * GRID);
    const int b  = idx / (CC * GRID * GRID);
    const int y = sp / GRID, x = sp - y * GRID;
    const int hh = c >> 6, d = c & 63;

    const size_t vbase = ((size_t)(b * HH + hh) * NT) * DH + d;
    float s = bias[c];
    #pragma unroll
    for (int ky = 0; ky < 3; ky++) {
        const int yy = y + ky - 1;
        if (yy < 0 || yy >= GRID) continue;
        #pragma unroll
        for (int kx = 0; kx < 3; kx++) {
            const int xx = x + kx - 1;
            if (xx < 0 || xx >= GRID) continue;
            const int t = 1 + yy * GRID + xx;
            s = fmaf(__half2float(vh[vbase + (size_t)t * DH]), wgt[c * 9 + ky * 3 + kx], s);
        }
    }
    const size_t oidx = ((size_t)b * NT + 1 + sp) * CC + c;
    const float a = __half2float(ah[oidx]) + __half2float(al[oidx]) + s;
    const __half hb = __float2half_rn(a);
    ah[oidx] = hb;
    al[oidx] = __float2half_rn(a - __half2float(hb));
}

// ---------------- launch ----------------
extern "C" void kernel_launch(void* const* d_in, const int* in_sizes, int n_in,
                              void* d_out, int out_size)
{
    const float* x      = (const float*)d_in[0];
    const float* W_qkv  = (const float*)d_in[1];
    const float* b_qkv  = (const float*)d_in[2];
    const float* W_proj = (const float*)d_in[3];
    const float* b_proj = (const float*)d_in[4];
    const float* dwc_w  = (const float*)d_in[5];
    const float* dwc_b  = (const float*)d_in[6];
    float* out = (float*)d_out;

    __half *qh, *ql, *kh, *vh, *ah, *al, *xh, *xl, *wqh, *wph;
    cudaGetSymbolAddress((void**)&qh,  g_qh);
    cudaGetSymbolAddress((void**)&ql,  g_ql);
    cudaGetSymbolAddress((void**)&kh,  g_kh);
    cudaGetSymbolAddress((void**)&vh,  g_vh);
    cudaGetSymbolAddress((void**)&ah,  g_ah);
    cudaGetSymbolAddress((void**)&al,  g_al);
    cudaGetSymbolAddress((void**)&xh,  g_xh);
    cudaGetSymbolAddress((void**)&xl,  g_xl);
    cudaGetSymbolAddress((void**)&wqh, g_wqh);
    cudaGetSymbolAddress((void**)&wph, g_wph);

    // 0) convert: x split hi/lo, weights hi only
    cvt_split_kernel<<<(M_ROWS * CC / 4) / 256, 256>>>(x, xh, xl);
    cvt_hi_kernel<<<(CC * 3 * CC / 4) / 256, 256>>>(W_qkv, wqh);
    cvt_hi_kernel<<<(CC * CC / 4) / 256, 256>>>(W_proj, wph);

    // 1) qkv projection -> q(scaled, hi/lo), k(hi), v(hi) in (B,H,N,D)
    {
        cudaFuncSetAttribute(mma_gemm_h<1>, cudaFuncAttributeMaxDynamicSharedMemorySize,
                             GS_TOTAL);
        dim3 grid(3 * CC / 128, M_ROWS / 128);
        mma_gemm_h<1><<<grid, 256, GS_TOTAL>>>(xh, xl, wqh, b_qkv, nullptr,
                                               qh, ql, kh, vh,
                                               M_ROWS, 3 * CC, CC);
    }

    // 2) fp16 tensor-core attention -> ah/al
    {
        const int smem_bytes = 4 * ATT_ELEMS * (int)sizeof(__half);  // 119808
        cudaFuncSetAttribute(attn_mma_kernel, cudaFuncAttributeMaxDynamicSharedMemorySize,
                             smem_bytes);
        attn_mma_kernel<<<Bv * HH, 416, smem_bytes>>>(qh, ql, kh, vh, ah, al);
    }

    // 3) depthwise conv + residual add into ah/al rows 1:
    {
        const int total = Bv * GRID * GRID * CC;
        dwconv_kernel<<<total / 256, 256>>>(vh, dwc_w, dwc_b, ah, al);
    }

    // 4) output projection (reads ah/al, wph)
    {
        cudaFuncSetAttribute(mma_gemm_h<0>, cudaFuncAttributeMaxDynamicSharedMemorySize,
                             GS_TOTAL);
        dim3 grid(CC / 128, M_ROWS / 128);
        mma_gemm_h<0><<<grid, 256, GS_TOTAL>>>(ah, al, wph, b_proj, out,
                                               nullptr, nullptr, nullptr, nullptr,
                                               M_ROWS, CC, CC);
    }
}

// round 13
// speedup vs baseline: 2.1995x; 2.1995x over previous
#include <cuda_runtime.h>
#include <cuda_fp16.h>
#include <math.h>

#define Bv 256
#define NT 197
#define CC 768
#define HH 12
#define DH 64
#define GRID 14
#define M_ROWS (Bv * NT)          // 50432 = 394*128

// ---------------- scratch ----------------
__device__ __half g_qh[(size_t)Bv * HH * NT * DH];
__device__ __half g_ql[(size_t)Bv * HH * NT * DH];
__device__ __half g_kh[(size_t)Bv * HH * NT * DH];
__device__ __half g_vh[(size_t)Bv * HH * NT * DH];
__device__ __half g_ah[(size_t)M_ROWS * CC];
__device__ __half g_xh[(size_t)M_ROWS * CC];
__device__ __half g_wqh[(size_t)CC * 3 * CC];
__device__ __half g_wph[(size_t)CC * CC];

// ---------------- helpers ----------------
__device__ __forceinline__ unsigned smem_u32(const void* p) {
    return (unsigned)__cvta_generic_to_shared(p);
}
__device__ __forceinline__ void cp_async16_u(unsigned s, const void* g) {
    asm volatile("cp.async.cg.shared.global [%0], [%1], 16;\n" :: "r"(s), "l"(g));
}
__device__ __forceinline__ void ldsm_x4(unsigned& r0, unsigned& r1, unsigned& r2, unsigned& r3,
                                        unsigned addr) {
    asm volatile("ldmatrix.sync.aligned.m8n8.x4.shared.b16 {%0,%1,%2,%3}, [%4];\n"
                 : "=r"(r0), "=r"(r1), "=r"(r2), "=r"(r3) : "r"(addr));
}
__device__ __forceinline__ void ldsm_x4t(unsigned& r0, unsigned& r1, unsigned& r2, unsigned& r3,
                                         unsigned addr) {
    asm volatile("ldmatrix.sync.aligned.m8n8.x4.trans.shared.b16 {%0,%1,%2,%3}, [%4];\n"
                 : "=r"(r0), "=r"(r1), "=r"(r2), "=r"(r3) : "r"(addr));
}
__device__ __forceinline__ void ldsm_x2t(unsigned& r0, unsigned& r1, unsigned addr) {
    asm volatile("ldmatrix.sync.aligned.m8n8.x2.trans.shared.b16 {%0,%1}, [%2];\n"
                 : "=r"(r0), "=r"(r1) : "r"(addr));
}
__device__ __forceinline__ void mma16816h(float* c, unsigned a0, unsigned a1, unsigned a2,
                                          unsigned a3, unsigned b0, unsigned b1) {
    asm volatile("mma.sync.aligned.m16n8k16.row.col.f32.f16.f16.f32 "
                 "{%0,%1,%2,%3}, {%4,%5,%6,%7}, {%8,%9}, {%0,%1,%2,%3};\n"
                 : "+f"(c[0]), "+f"(c[1]), "+f"(c[2]), "+f"(c[3])
                 : "r"(a0), "r"(a1), "r"(a2), "r"(a3), "r"(b0), "r"(b1));
}
__device__ __forceinline__ void split2h(float x, float y, __half2& h, __half2& l) {
    h.x = __float2half_rn(x); l.x = __float2half_rn(x - __half2float(h.x));
    h.y = __float2half_rn(y); l.y = __float2half_rn(y - __half2float(h.y));
}
__device__ __forceinline__ unsigned pack_hi_h(float x, float y) {
    __half2 t; t.x = __float2half_rn(x); t.y = __float2half_rn(y);
    return *reinterpret_cast<unsigned*>(&t);
}
__device__ __forceinline__ unsigned pack_lo_h(float x, float y) {
    __half hx = __float2half_rn(x);
    __half hy = __float2half_rn(y);
    __half2 t;
    t.x = __float2half_rn(x - __half2float(hx));
    t.y = __float2half_rn(y - __half2float(hy));
    return *reinterpret_cast<unsigned*>(&t);
}

// ---------------- convert kernel (fp32 -> fp16) ----------------
__global__ __launch_bounds__(256)
void cvt_hi_kernel(const float* __restrict__ src, __half* __restrict__ hi)
{
    const int i = blockIdx.x * 256 + threadIdx.x;
    float4 v = reinterpret_cast<const float4*>(src)[i];
    __half2 h0, h1;
    h0.x = __float2half_rn(v.x); h0.y = __float2half_rn(v.y);
    h1.x = __float2half_rn(v.z); h1.y = __float2half_rn(v.w);
    reinterpret_cast<__half2*>(hi + (size_t)i * 4)[0] = h0;
    reinterpret_cast<__half2*>(hi + (size_t)i * 4)[1] = h1;
}

// ---------------- fp16 GEMM: 128x128x32 CTA, 256 threads, 2-stage (R9 structure) ----------------
#define LDA 40    // 32 + 8 pad (fp16)
#define LDB 136   // 128 + 8 pad

template<int MODE>
__global__ __launch_bounds__(256, 2)
void mma_gemm_h(const __half* __restrict__ Agh,
                const __half* __restrict__ Bgh,
                const float* __restrict__ bias, float* __restrict__ C,
                __half* __restrict__ Qh, __half* __restrict__ Ql,
                __half* __restrict__ Kh, __half* __restrict__ Vh,
                int M, int N, int K)
{
    __shared__ alignas(16) __half sA[2][128][LDA];
    __shared__ alignas(16) __half sB[2][32][LDB];

    const int tid  = threadIdx.x;
    const int brow = blockIdx.y;
    const int bcol = blockIdx.x;
    const int lane = tid & 31;
    const int wid  = tid >> 5;
    const int wm = (wid & 1) * 64;
    const int wn = (wid >> 1) * 32;
    const int aRowBase = brow * 128;
    const int bColBase = bcol * 128;

    float acc[4][4][4];
    #pragma unroll
    for (int mt = 0; mt < 4; mt++)
        #pragma unroll
        for (int nt = 0; nt < 4; nt++)
            #pragma unroll
            for (int e = 0; e < 4; e++) acc[mt][nt][e] = 0.f;

    const int aRowLane = lane & 15;
    const int aColLane = (lane >> 4) << 3;
    const int bRowLane = lane & 15;

    auto issue = [&](int k0, int st) {
        // A: 512 chunks of 16B (128 rows x 4 chunks of 8 halves)
        #pragma unroll
        for (int c = 0; c < 2; c++) {
            const int chunk = tid + c * 256;          // 0..511
            const int arow = chunk >> 2;
            const int acol = (chunk & 3) << 3;
            const size_t aoff = (size_t)(aRowBase + arow) * K + k0 + acol;
            cp_async16_u(smem_u32(&sA[st][arow][acol]), Agh + aoff);
        }
        // B: 512 chunks of 16B
        #pragma unroll
        for (int c = 0; c < 2; c++) {
            const int chunk = tid + c * 256;          // 0..511
            const int brw = chunk >> 4;
            const int bcl = (chunk & 15) << 3;
            const size_t boff = (size_t)(k0 + brw) * N + bColBase + bcl;
            cp_async16_u(smem_u32(&sB[st][brw][bcl]), Bgh + boff);
        }
        asm volatile("cp.async.commit_group;\n");
    };

    const int NIT = K >> 5;
    issue(0, 0);

    for (int it = 0; it < NIT; ++it) {
        if (it + 1 < NIT) {
            issue((it + 1) << 5, (it + 1) & 1);
            asm volatile("cp.async.wait_group 1;\n");
        } else {
            asm volatile("cp.async.wait_group 0;\n");
        }
        __syncthreads();

        const int st = it & 1;
        const unsigned aBaseH = smem_u32(&sA[st][0][0]);
        const unsigned bBaseH = smem_u32(&sB[st][0][0]);

        #pragma unroll
        for (int ks = 0; ks < 2; ks++) {
            unsigned bhf[4][2];
            #pragma unroll
            for (int nt = 0; nt < 4; nt++) {
                const unsigned boff = ((ks * 16 + bRowLane) * LDB + wn + nt * 8) * 2;
                ldsm_x2t(bhf[nt][0], bhf[nt][1], bBaseH + boff);
            }
            #pragma unroll
            for (int mt = 0; mt < 4; mt++) {
                const unsigned aoff = ((wm + mt * 16 + aRowLane) * LDA + ks * 16 + aColLane) * 2;
                unsigned ah0, ah1, ah2, ah3;
                ldsm_x4(ah0, ah1, ah2, ah3, aBaseH + aoff);
                #pragma unroll
                for (int nt = 0; nt < 4; nt++) {
                    mma16816h(acc[mt][nt], ah0, ah1, ah2, ah3, bhf[nt][0], bhf[nt][1]);
                }
            }
        }
        __syncthreads();
    }

    const int trow = lane >> 2;
    const int tcol = (lane & 3) << 1;
    #pragma unroll
    for (int mt = 0; mt < 4; mt++) {
        #pragma unroll
        for (int nt = 0; nt < 4; nt++) {
            const int gc = bColBase + wn + nt * 8 + tcol;
            const float bia0 = bias[gc];
            const float bia1 = bias[gc + 1];
            #pragma unroll
            for (int half_ = 0; half_ < 2; half_++) {
                const int gr = aRowBase + wm + mt * 16 + trow + half_ * 8;
                float2 val;
                val.x = acc[mt][nt][half_ * 2 + 0] + bia0;
                val.y = acc[mt][nt][half_ * 2 + 1] + bia1;
                if (MODE == 0) {
                    *(float2*)&C[(size_t)gr * N + gc] = val;
                } else {
                    const int b_ = gr / NT;
                    const int t  = gr - b_ * NT;
                    const int s  = gc / CC;
                    const int r  = gc - s * CC;
                    const int hh = r >> 6;
                    const int d  = r & 63;
                    const size_t idx2 = (((size_t)((b_ * HH + hh) * NT + t)) * DH + d) >> 1;
                    if (s == 0) {
                        val.x *= 0.125f; val.y *= 0.125f;
                        __half2 h2, l2;
                        split2h(val.x, val.y, h2, l2);
                        reinterpret_cast<__half2*>(Qh)[idx2] = h2;
                        reinterpret_cast<__half2*>(Ql)[idx2] = l2;
                    } else {
                        __half2 h2;
                        h2.x = __float2half_rn(val.x);
                        h2.y = __float2half_rn(val.y);
                        reinterpret_cast<__half2*>((s == 1) ? Kh : Vh)[idx2] = h2;
                    }
                }
            }
        }
    }
}

// ---------------- fp16 tensor-core attention: one CTA per (b,h), 416 threads ----------------
#define ATT_ROWS 208
#define ATT_LD 72
#define ATT_ELEMS (ATT_ROWS * ATT_LD)   // 14976

__global__ __launch_bounds__(416, 1)
void attn_mma_kernel(const __half* __restrict__ qh, const __half* __restrict__ ql,
                     const __half* __restrict__ kh, const __half* __restrict__ vh,
                     __half* __restrict__ outh)
{
    extern __shared__ __half sm[];
    __half* smQH = sm;
    __half* smQL = sm + ATT_ELEMS;
    __half* smKH = sm + 2 * ATT_ELEMS;
    __half* smVH = sm + 3 * ATT_ELEMS;

    const int bh = blockIdx.x;
    const int b  = bh / HH;
    const int h  = bh - b * HH;
    const size_t base = (size_t)bh * NT * DH;
    const int tid  = threadIdx.x;
    const int lane = tid & 31;
    const int wid  = tid >> 5;     // 0..12

    const unsigned uQH = smem_u32(smQH);
    const unsigned uQL = smem_u32(smQL);
    const unsigned uKH = smem_u32(smKH);
    const unsigned uVH = smem_u32(smVH);

    for (int i = tid; i < NT * 8; i += 416) {      // 197 rows x 8 chunks
        const int row = i >> 3;
        const int j = i & 7;
        const unsigned doff = (unsigned)((row * ATT_LD + j * 8) * 2);
        const size_t soff = base + (size_t)row * DH + j * 8;
        cp_async16_u(uQH + doff, qh + soff);
        cp_async16_u(uQL + doff, ql + soff);
        cp_async16_u(uKH + doff, kh + soff);
        cp_async16_u(uVH + doff, vh + soff);
    }
    const float4 z4 = make_float4(0.f, 0.f, 0.f, 0.f);
    for (int i = tid; i < 11 * 8; i += 416) {
        const int row = NT + (i >> 3);
        const int j = i & 7;
        const int off = row * ATT_LD + j * 8;
        *(float4*)&smQH[off] = z4; *(float4*)&smQL[off] = z4;
        *(float4*)&smKH[off] = z4; *(float4*)&smVH[off] = z4;
    }
    asm volatile("cp.async.commit_group;\n");
    asm volatile("cp.async.wait_group 0;\n");
    __syncthreads();

    const int m0 = wid * 16;

    unsigned qf[4][4], qg[4][4];
    {
        const int r  = m0 + (lane & 15);
        const int cb = (lane >> 4) << 3;
        #pragma unroll
        for (int ks = 0; ks < 4; ks++) {
            const unsigned off = (unsigned)((r * ATT_LD + ks * 16 + cb) * 2);
            ldsm_x4(qf[ks][0], qf[ks][1], qf[ks][2], qf[ks][3], uQH + off);
            ldsm_x4(qg[ks][0], qg[ks][1], qg[ks][2], qg[ks][3], uQL + off);
        }
    }

    float s[25][4];
    #pragma unroll
    for (int nt = 0; nt < 25; nt++)
        #pragma unroll
        for (int e = 0; e < 4; e++) s[nt][e] = 0.f;

    const int krow = lane & 7;
    const int kcol = ((lane >> 3) & 3) << 3;
    #pragma unroll
    for (int nt = 0; nt < 25; nt++) {
        const int n0 = nt * 8;
        unsigned khf[4][2];
        {
            const unsigned o1 = (unsigned)(((n0 + krow) * ATT_LD + kcol) * 2);
            unsigned r0, r1, r2, r3;
            ldsm_x4(r0, r1, r2, r3, uKH + o1);
            khf[0][0] = r0; khf[0][1] = r1; khf[1][0] = r2; khf[1][1] = r3;
            ldsm_x4(r0, r1, r2, r3, uKH + o1 + 64);
            khf[2][0] = r0; khf[2][1] = r1; khf[3][0] = r2; khf[3][1] = r3;
        }
        #pragma unroll
        for (int ks = 0; ks < 4; ks++) {
            mma16816h(s[nt], qf[ks][0], qf[ks][1], qf[ks][2], qf[ks][3], khf[ks][0], khf[ks][1]);
            mma16816h(s[nt], qg[ks][0], qg[ks][1], qg[ks][2], qg[ks][3], khf[ks][0], khf[ks][1]);
        }
    }

    {
        const int col0 = 192 + ((lane & 3) << 1);
        if (col0     >= NT) { s[24][0] = -1e30f; s[24][2] = -1e30f; }
        if (col0 + 1 >= NT) { s[24][1] = -1e30f; s[24][3] = -1e30f; }
    }
    float mx0 = -1e30f, mx1 = -1e30f;
    #pragma unroll
    for (int nt = 0; nt < 25; nt++) {
        mx0 = fmaxf(mx0, fmaxf(s[nt][0], s[nt][1]));
        mx1 = fmaxf(mx1, fmaxf(s[nt][2], s[nt][3]));
    }
    mx0 = fmaxf(mx0, __shfl_xor_sync(0xffffffffu, mx0, 1));
    mx0 = fmaxf(mx0, __shfl_xor_sync(0xffffffffu, mx0, 2));
    mx1 = fmaxf(mx1, __shfl_xor_sync(0xffffffffu, mx1, 1));
    mx1 = fmaxf(mx1, __shfl_xor_sync(0xffffffffu, mx1, 2));

    float sum0 = 0.f, sum1 = 0.f;
    #pragma unroll
    for (int nt = 0; nt < 25; nt++) {
        const float e0 = __expf(s[nt][0] - mx0);
        const float e1 = __expf(s[nt][1] - mx0);
        const float e2 = __expf(s[nt][2] - mx1);
        const float e3 = __expf(s[nt][3] - mx1);
        s[nt][0] = e0; s[nt][1] = e1; s[nt][2] = e2; s[nt][3] = e3;
        sum0 += e0 + e1; sum1 += e2 + e3;
    }
    sum0 += __shfl_xor_sync(0xffffffffu, sum0, 1);
    sum0 += __shfl_xor_sync(0xffffffffu, sum0, 2);
    sum1 += __shfl_xor_sync(0xffffffffu, sum1, 1);
    sum1 += __shfl_xor_sync(0xffffffffu, sum1, 2);
    const float inv0 = 1.0f / sum0;
    const float inv1 = 1.0f / sum1;

    float o[8][4];
    #pragma unroll
    for (int nt = 0; nt < 8; nt++)
        #pragma unroll
        for (int e = 0; e < 4; e++) o[nt][e] = 0.f;

    const int vrow = ((lane >> 3) & 1) * 8 + (lane & 7);
    const int vcol = (lane >> 4) << 3;
    #pragma unroll
    for (int ks = 0; ks < 13; ks++) {
        unsigned ah0, ah1, ah2, ah3, al0, al1, al2, al3;
        if (ks < 12) {
            ah0 = pack_hi_h(s[2*ks][0],   s[2*ks][1]);   ah1 = pack_hi_h(s[2*ks][2],   s[2*ks][3]);
            ah2 = pack_hi_h(s[2*ks+1][0], s[2*ks+1][1]); ah3 = pack_hi_h(s[2*ks+1][2], s[2*ks+1][3]);
            al0 = pack_lo_h(s[2*ks][0],   s[2*ks][1]);   al1 = pack_lo_h(s[2*ks][2],   s[2*ks][3]);
            al2 = pack_lo_h(s[2*ks+1][0], s[2*ks+1][1]); al3 = pack_lo_h(s[2*ks+1][2], s[2*ks+1][3]);
        } else {
            ah0 = pack_hi_h(s[24][0], s[24][1]); ah1 = pack_hi_h(s[24][2], s[24][3]);
            al0 = pack_lo_h(s[24][0], s[24][1]); al1 = pack_lo_h(s[24][2], s[24][3]);
            ah2 = 0u; ah3 = 0u; al2 = 0u; al3 = 0u;
        }
        const int k0 = ks * 16;
        #pragma unroll
        for (int np = 0; np < 4; np++) {
            const unsigned off = (unsigned)(((k0 + vrow) * ATT_LD + np * 16 + vcol) * 2);
            unsigned vh0, vh1, vh2, vh3;
            ldsm_x4t(vh0, vh1, vh2, vh3, uVH + off);
            mma16816h(o[2 * np],     ah0, ah1, ah2, ah3, vh0, vh1);
            mma16816h(o[2 * np],     al0, al1, al2, al3, vh0, vh1);
            mma16816h(o[2 * np + 1], ah0, ah1, ah2, ah3, vh2, vh3);
            mma16816h(o[2 * np + 1], al0, al1, al2, al3, vh2, vh3);
        }
    }

    const int r0 = m0 + (lane >> 2);
    const int r1 = r0 + 8;
    const int cb = h * DH + ((lane & 3) << 1);
    if (r0 < NT) {
        const size_t ob = (((size_t)b * NT + r0) * CC + cb) >> 1;
        #pragma unroll
        for (int nt = 0; nt < 8; nt++) {
            __half2 h2;
            h2.x = __float2half_rn(o[nt][0] * inv0);
            h2.y = __float2half_rn(o[nt][1] * inv0);
            reinterpret_cast<__half2*>(outh)[ob + nt * 4] = h2;
        }
    }
    if (r1 < NT) {
        const size_t ob = (((size_t)b * NT + r1) * CC + cb) >> 1;
        #pragma unroll
        for (int nt = 0; nt < 8; nt++) {
            __half2 h2;
            h2.x = __float2half_rn(o[nt][2] * inv1);
            h2.y = __float2half_rn(o[nt][3] * inv1);
            reinterpret_cast<__half2*>(outh)[ob + nt * 4] = h2;
        }
    }
}

// ---------------- depthwise 3x3 conv on V (tokens 1:), residual add ----------------
__global__ __launch_bounds__(256)
void dwconv_kernel(const __half* __restrict__ vh,
                   const float* __restrict__ wgt, const float* __restrict__ bias,
                   __half* __restrict__ ah)
{
    const int idx = blockIdx.x * 256 + threadIdx.x;
    const int c  = idx % CC;
    const int sp = (idx / CC) % (GRID * GRID);
    const int b  = idx / (CC * GRID * GRID);
    const int y = sp / GRID, x = sp - y * GRID;
    const int hh = c >> 6, d = c & 63;

    const size_t vbase = ((size_t)(b * HH + hh) * NT) * DH + d;
    float s = bias[c];
    #pragma unroll
    for (int ky = 0; ky < 3; ky++) {
        const int yy = y + ky - 1;
        if (yy < 0 || yy >= GRID) continue;
        #pragma unroll
        for (int kx = 0; kx < 3; kx++) {
            const int xx = x + kx - 1;
            if (xx < 0 || xx >= GRID) continue;
            const int t = 1 + yy * GRID + xx;
            s = fmaf(__half2float(vh[vbase + (size_t)t * DH]), wgt[c * 9 + ky * 3 + kx], s);
        }
    }
    const size_t oidx = ((size_t)b * NT + 1 + sp) * CC + c;
    ah[oidx] = __float2half_rn(__half2float(ah[oidx]) + s);
}

// ---------------- launch ----------------
extern "C" void kernel_launch(void* const* d_in, const int* in_sizes, int n_in,
                              void* d_out, int out_size)
{
    const float* x      = (const float*)d_in[0];
    const float* W_qkv  = (const float*)d_in[1];
    const float* b_qkv  = (const float*)d_in[2];
    const float* W_proj = (const float*)d_in[3];
    const float* b_proj = (const float*)d_in[4];
    const float* dwc_w  = (const float*)d_in[5];
    const float* dwc_b  = (const float*)d_in[6];
    float* out = (float*)d_out;

    __half *qh, *ql, *kh, *vh, *ah, *xh, *wqh, *wph;
    cudaGetSymbolAddress((void**)&qh,  g_qh);
    cudaGetSymbolAddress((void**)&ql,  g_ql);
    cudaGetSymbolAddress((void**)&kh,  g_kh);
    cudaGetSymbolAddress((void**)&vh,  g_vh);
    cudaGetSymbolAddress((void**)&ah,  g_ah);
    cudaGetSymbolAddress((void**)&xh,  g_xh);
    cudaGetSymbolAddress((void**)&wqh, g_wqh);
    cudaGetSymbolAddress((void**)&wph, g_wph);

    // 0) convert all fp32 operands to fp16
    cvt_hi_kernel<<<(M_ROWS * CC / 4) / 256, 256>>>(x, xh);
    cvt_hi_kernel<<<(CC * 3 * CC / 4) / 256, 256>>>(W_qkv, wqh);
    cvt_hi_kernel<<<(CC * CC / 4) / 256, 256>>>(W_proj, wph);

    // 1) qkv projection (single-stream fp16) -> q(scaled, hi/lo), k, v in (B,H,N,D)
    {
        dim3 grid(3 * CC / 128, M_ROWS / 128);
        mma_gemm_h<1><<<grid, 256>>>(xh, wqh, b_qkv, nullptr,
                                     qh, ql, kh, vh,
                                     M_ROWS, 3 * CC, CC);
    }

    // 2) fp16 tensor-core attention -> ah
    {
        const int smem_bytes = 4 * ATT_ELEMS * (int)sizeof(__half);  // 119808
        cudaFuncSetAttribute(attn_mma_kernel, cudaFuncAttributeMaxDynamicSharedMemorySize,
                             smem_bytes);
        attn_mma_kernel<<<Bv * HH, 416, smem_bytes>>>(qh, ql, kh, vh, ah);
    }

    // 3) depthwise conv + residual add into ah rows 1:
    {
        const int total = Bv * GRID * GRID * CC;
        dwconv_kernel<<<total / 256, 256>>>(vh, dwc_w, dwc_b, ah);
    }

    // 4) output projection (single-stream fp16)
    {
        dim3 grid(CC / 128, M_ROWS / 128);
        mma_gemm_h<0><<<grid, 256>>>(ah, wph, b_proj, out,
                                     nullptr, nullptr, nullptr, nullptr,
                                     M_ROWS, CC, CC);
    }
}

// round 14
// speedup vs baseline: 2.4243x; 1.1022x over previous
#include <cuda_runtime.h>
#include <cuda_fp16.h>
#include <math.h>

#define Bv 256
#define NT 197
#define CC 768
#define HH 12
#define DH 64
#define GRID 14
#define M_ROWS (Bv * NT)          // 50432 = 394*128

// ---------------- scratch ----------------
__device__ __half g_qh[(size_t)Bv * HH * NT * DH];
__device__ __half g_ql[(size_t)Bv * HH * NT * DH];
__device__ __half g_kh[(size_t)Bv * HH * NT * DH];
__device__ __half g_vh[(size_t)Bv * HH * NT * DH];
__device__ __half g_ah[(size_t)M_ROWS * CC];
__device__ __half g_xh[(size_t)M_ROWS * CC];
__device__ __half g_wqh[(size_t)CC * 3 * CC];
__device__ __half g_wph[(size_t)CC * CC];

// ---------------- helpers ----------------
__device__ __forceinline__ unsigned smem_u32(const void* p) {
    return (unsigned)__cvta_generic_to_shared(p);
}
__device__ __forceinline__ void cp_async16_u(unsigned s, const void* g) {
    asm volatile("cp.async.cg.shared.global [%0], [%1], 16;\n" :: "r"(s), "l"(g));
}
__device__ __forceinline__ void ldsm_x4(unsigned& r0, unsigned& r1, unsigned& r2, unsigned& r3,
                                        unsigned addr) {
    asm volatile("ldmatrix.sync.aligned.m8n8.x4.shared.b16 {%0,%1,%2,%3}, [%4];\n"
                 : "=r"(r0), "=r"(r1), "=r"(r2), "=r"(r3) : "r"(addr));
}
__device__ __forceinline__ void ldsm_x4t(unsigned& r0, unsigned& r1, unsigned& r2, unsigned& r3,
                                         unsigned addr) {
    asm volatile("ldmatrix.sync.aligned.m8n8.x4.trans.shared.b16 {%0,%1,%2,%3}, [%4];\n"
                 : "=r"(r0), "=r"(r1), "=r"(r2), "=r"(r3) : "r"(addr));
}
__device__ __forceinline__ void ldsm_x2t(unsigned& r0, unsigned& r1, unsigned addr) {
    asm volatile("ldmatrix.sync.aligned.m8n8.x2.trans.shared.b16 {%0,%1}, [%2];\n"
                 : "=r"(r0), "=r"(r1) : "r"(addr));
}
__device__ __forceinline__ void mma16816h(float* c, unsigned a0, unsigned a1, unsigned a2,
                                          unsigned a3, unsigned b0, unsigned b1) {
    asm volatile("mma.sync.aligned.m16n8k16.row.col.f32.f16.f16.f32 "
                 "{%0,%1,%2,%3}, {%4,%5,%6,%7}, {%8,%9}, {%0,%1,%2,%3};\n"
                 : "+f"(c[0]), "+f"(c[1]), "+f"(c[2]), "+f"(c[3])
                 : "r"(a0), "r"(a1), "r"(a2), "r"(a3), "r"(b0), "r"(b1));
}
__device__ __forceinline__ void split2h(float x, float y, __half2& h, __half2& l) {
    h.x = __float2half_rn(x); l.x = __float2half_rn(x - __half2float(h.x));
    h.y = __float2half_rn(y); l.y = __float2half_rn(y - __half2float(h.y));
}
__device__ __forceinline__ unsigned pack_hi_h(float x, float y) {
    __half2 t; t.x = __float2half_rn(x); t.y = __float2half_rn(y);
    return *reinterpret_cast<unsigned*>(&t);
}

// ---------------- convert kernel (fp32 -> fp16) ----------------
__global__ __launch_bounds__(256)
void cvt_hi_kernel(const float* __restrict__ src, __half* __restrict__ hi)
{
    const int i = blockIdx.x * 256 + threadIdx.x;
    float4 v = reinterpret_cast<const float4*>(src)[i];
    __half2 h0, h1;
    h0.x = __float2half_rn(v.x); h0.y = __float2half_rn(v.y);
    h1.x = __float2half_rn(v.z); h1.y = __float2half_rn(v.w);
    reinterpret_cast<__half2*>(hi + (size_t)i * 4)[0] = h0;
    reinterpret_cast<__half2*>(hi + (size_t)i * 4)[1] = h1;
}

// ---------------- fp16 GEMM: 128x128x64 CTA, 256 threads, 2-stage ----------------
#define LDA2 72   // 64 + 8 pad (fp16)
#define LDB2 136  // 128 + 8 pad
#define G2_A   (128 * LDA2 * 2)               // 18432 B
#define G2_B   (64 * LDB2 * 2)                // 17408 B
#define G2_STAGE (G2_A + G2_B)                // 35840 B
#define G2_TOTAL (2 * G2_STAGE)               // 71680 B

template<int MODE>
__global__ __launch_bounds__(256, 2)
void mma_gemm_h(const __half* __restrict__ Agh,
                const __half* __restrict__ Bgh,
                const float* __restrict__ bias, float* __restrict__ C,
                __half* __restrict__ Qh, __half* __restrict__ Ql,
                __half* __restrict__ Kh, __half* __restrict__ Vh,
                int M, int N, int K)
{
    extern __shared__ char gsm[];
    const unsigned smBase = smem_u32(gsm);

    const int tid  = threadIdx.x;
    const int brow = blockIdx.y;
    const int bcol = blockIdx.x;
    const int lane = tid & 31;
    const int wid  = tid >> 5;
    const int wm = (wid & 1) * 64;
    const int wn = (wid >> 1) * 32;
    const int aRowBase = brow * 128;
    const int bColBase = bcol * 128;

    float acc[4][4][4];
    #pragma unroll
    for (int mt = 0; mt < 4; mt++)
        #pragma unroll
        for (int nt = 0; nt < 4; nt++)
            #pragma unroll
            for (int e = 0; e < 4; e++) acc[mt][nt][e] = 0.f;

    const int aRowLane = lane & 15;
    const int aColLane = (lane >> 4) << 3;
    const int bRowLane = lane & 15;

    auto issue = [&](int k0, int st) {
        const unsigned stBase = smBase + st * G2_STAGE;
        // A: 128 rows x 64 halves = 1024 chunks of 8 halves -> 4 per thread
        #pragma unroll
        for (int c = 0; c < 4; c++) {
            const int chunk = tid + c * 256;          // 0..1023
            const int arow = chunk >> 3;
            const int acol = (chunk & 7) << 3;
            const size_t aoff = (size_t)(aRowBase + arow) * K + k0 + acol;
            cp_async16_u(stBase + (arow * LDA2 + acol) * 2, Agh + aoff);
        }
        // B: 64 rows x 128 halves = 1024 chunks -> 4 per thread
        #pragma unroll
        for (int c = 0; c < 4; c++) {
            const int chunk = tid + c * 256;          // 0..1023
            const int brw = chunk >> 4;
            const int bcl = (chunk & 15) << 3;
            const size_t boff = (size_t)(k0 + brw) * N + bColBase + bcl;
            cp_async16_u(stBase + G2_A + (brw * LDB2 + bcl) * 2, Bgh + boff);
        }
        asm volatile("cp.async.commit_group;\n");
    };

    const int NIT = K >> 6;   // K-stage 64
    issue(0, 0);

    for (int it = 0; it < NIT; ++it) {
        if (it + 1 < NIT) {
            issue((it + 1) << 6, (it + 1) & 1);
            asm volatile("cp.async.wait_group 1;\n");
        } else {
            asm volatile("cp.async.wait_group 0;\n");
        }
        __syncthreads();

        const unsigned stBase = smBase + (it & 1) * G2_STAGE;
        const unsigned aBaseH = stBase;
        const unsigned bBaseH = stBase + G2_A;

        #pragma unroll
        for (int ks = 0; ks < 4; ks++) {
            unsigned bhf[4][2];
            #pragma unroll
            for (int nt = 0; nt < 4; nt++) {
                const unsigned boff = ((ks * 16 + bRowLane) * LDB2 + wn + nt * 8) * 2;
                ldsm_x2t(bhf[nt][0], bhf[nt][1], bBaseH + boff);
            }
            #pragma unroll
            for (int mt = 0; mt < 4; mt++) {
                const unsigned aoff = ((wm + mt * 16 + aRowLane) * LDA2 + ks * 16 + aColLane) * 2;
                unsigned ah0, ah1, ah2, ah3;
                ldsm_x4(ah0, ah1, ah2, ah3, aBaseH + aoff);
                #pragma unroll
                for (int nt = 0; nt < 4; nt++) {
                    mma16816h(acc[mt][nt], ah0, ah1, ah2, ah3, bhf[nt][0], bhf[nt][1]);
                }
            }
        }
        __syncthreads();
    }

    const int trow = lane >> 2;
    const int tcol = (lane & 3) << 1;
    #pragma unroll
    for (int mt = 0; mt < 4; mt++) {
        #pragma unroll
        for (int nt = 0; nt < 4; nt++) {
            const int gc = bColBase + wn + nt * 8 + tcol;
            const float bia0 = bias[gc];
            const float bia1 = bias[gc + 1];
            #pragma unroll
            for (int half_ = 0; half_ < 2; half_++) {
                const int gr = aRowBase + wm + mt * 16 + trow + half_ * 8;
                float2 val;
                val.x = acc[mt][nt][half_ * 2 + 0] + bia0;
                val.y = acc[mt][nt][half_ * 2 + 1] + bia1;
                if (MODE == 0) {
                    *(float2*)&C[(size_t)gr * N + gc] = val;
                } else {
                    const int b_ = gr / NT;
                    const int t  = gr - b_ * NT;
                    const int s  = gc / CC;
                    const int r  = gc - s * CC;
                    const int hh = r >> 6;
                    const int d  = r & 63;
                    const size_t idx2 = (((size_t)((b_ * HH + hh) * NT + t)) * DH + d) >> 1;
                    if (s == 0) {
                        val.x *= 0.125f; val.y *= 0.125f;
                        __half2 h2, l2;
                        split2h(val.x, val.y, h2, l2);
                        reinterpret_cast<__half2*>(Qh)[idx2] = h2;
                        reinterpret_cast<__half2*>(Ql)[idx2] = l2;
                    } else {
                        __half2 h2;
                        h2.x = __float2half_rn(val.x);
                        h2.y = __float2half_rn(val.y);
                        reinterpret_cast<__half2*>((s == 1) ? Kh : Vh)[idx2] = h2;
                    }
                }
            }
        }
    }
}

// ---------------- fp16 tensor-core attention: one CTA per (b,h), 416 threads ----------------
#define ATT_ROWS 208
#define ATT_LD 72
#define ATT_ELEMS (ATT_ROWS * ATT_LD)   // 14976

__global__ __launch_bounds__(416, 1)
void attn_mma_kernel(const __half* __restrict__ qh, const __half* __restrict__ ql,
                     const __half* __restrict__ kh, const __half* __restrict__ vh,
                     __half* __restrict__ outh)
{
    extern __shared__ __half sm[];
    __half* smQH = sm;
    __half* smQL = sm + ATT_ELEMS;
    __half* smKH = sm + 2 * ATT_ELEMS;
    __half* smVH = sm + 3 * ATT_ELEMS;

    const int bh = blockIdx.x;
    const int b  = bh / HH;
    const int h  = bh - b * HH;
    const size_t base = (size_t)bh * NT * DH;
    const int tid  = threadIdx.x;
    const int lane = tid & 31;
    const int wid  = tid >> 5;     // 0..12

    const unsigned uQH = smem_u32(smQH);
    const unsigned uQL = smem_u32(smQL);
    const unsigned uKH = smem_u32(smKH);
    const unsigned uVH = smem_u32(smVH);

    for (int i = tid; i < NT * 8; i += 416) {      // 197 rows x 8 chunks
        const int row = i >> 3;
        const int j = i & 7;
        const unsigned doff = (unsigned)((row * ATT_LD + j * 8) * 2);
        const size_t soff = base + (size_t)row * DH + j * 8;
        cp_async16_u(uQH + doff, qh + soff);
        cp_async16_u(uQL + doff, ql + soff);
        cp_async16_u(uKH + doff, kh + soff);
        cp_async16_u(uVH + doff, vh + soff);
    }
    const float4 z4 = make_float4(0.f, 0.f, 0.f, 0.f);
    for (int i = tid; i < 11 * 8; i += 416) {
        const int row = NT + (i >> 3);
        const int j = i & 7;
        const int off = row * ATT_LD + j * 8;
        *(float4*)&smQH[off] = z4; *(float4*)&smQL[off] = z4;
        *(float4*)&smKH[off] = z4; *(float4*)&smVH[off] = z4;
    }
    asm volatile("cp.async.commit_group;\n");
    asm volatile("cp.async.wait_group 0;\n");
    __syncthreads();

    const int m0 = wid * 16;

    unsigned qf[4][4], qg[4][4];
    {
        const int r  = m0 + (lane & 15);
        const int cb = (lane >> 4) << 3;
        #pragma unroll
        for (int ks = 0; ks < 4; ks++) {
            const unsigned off = (unsigned)((r * ATT_LD + ks * 16 + cb) * 2);
            ldsm_x4(qf[ks][0], qf[ks][1], qf[ks][2], qf[ks][3], uQH + off);
            ldsm_x4(qg[ks][0], qg[ks][1], qg[ks][2], qg[ks][3], uQL + off);
        }
    }

    float s[25][4];
    #pragma unroll
    for (int nt = 0; nt < 25; nt++)
        #pragma unroll
        for (int e = 0; e < 4; e++) s[nt][e] = 0.f;

    const int krow = lane & 7;
    const int kcol = ((lane >> 3) & 3) << 3;
    #pragma unroll
    for (int nt = 0; nt < 25; nt++) {
        const int n0 = nt * 8;
        unsigned khf[4][2];
        {
            const unsigned o1 = (unsigned)(((n0 + krow) * ATT_LD + kcol) * 2);
            unsigned r0, r1, r2, r3;
            ldsm_x4(r0, r1, r2, r3, uKH + o1);
            khf[0][0] = r0; khf[0][1] = r1; khf[1][0] = r2; khf[1][1] = r3;
            ldsm_x4(r0, r1, r2, r3, uKH + o1 + 64);
            khf[2][0] = r0; khf[2][1] = r1; khf[3][0] = r2; khf[3][1] = r3;
        }
        #pragma unroll
        for (int ks = 0; ks < 4; ks++) {
            mma16816h(s[nt], qf[ks][0], qf[ks][1], qf[ks][2], qf[ks][3], khf[ks][0], khf[ks][1]);
            mma16816h(s[nt], qg[ks][0], qg[ks][1], qg[ks][2], qg[ks][3], khf[ks][0], khf[ks][1]);
        }
    }

    {
        const int col0 = 192 + ((lane & 3) << 1);
        if (col0     >= NT) { s[24][0] = -1e30f; s[24][2] = -1e30f; }
        if (col0 + 1 >= NT) { s[24][1] = -1e30f; s[24][3] = -1e30f; }
    }
    float mx0 = -1e30f, mx1 = -1e30f;
    #pragma unroll
    for (int nt = 0; nt < 25; nt++) {
        mx0 = fmaxf(mx0, fmaxf(s[nt][0], s[nt][1]));
        mx1 = fmaxf(mx1, fmaxf(s[nt][2], s[nt][3]));
    }
    mx0 = fmaxf(mx0, __shfl_xor_sync(0xffffffffu, mx0, 1));
    mx0 = fmaxf(mx0, __shfl_xor_sync(0xffffffffu, mx0, 2));
    mx1 = fmaxf(mx1, __shfl_xor_sync(0xffffffffu, mx1, 1));
    mx1 = fmaxf(mx1, __shfl_xor_sync(0xffffffffu, mx1, 2));

    float sum0 = 0.f, sum1 = 0.f;
    #pragma unroll
    for (int nt = 0; nt < 25; nt++) {
        const float e0 = __expf(s[nt][0] - mx0);
        const float e1 = __expf(s[nt][1] - mx0);
        const float e2 = __expf(s[nt][2] - mx1);
        const float e3 = __expf(s[nt][3] - mx1);
        s[nt][0] = e0; s[nt][1] = e1; s[nt][2] = e2; s[nt][3] = e3;
        sum0 += e0 + e1; sum1 += e2 + e3;
    }
    sum0 += __shfl_xor_sync(0xffffffffu, sum0, 1);
    sum0 += __shfl_xor_sync(0xffffffffu, sum0, 2);
    sum1 += __shfl_xor_sync(0xffffffffu, sum1, 1);
    sum1 += __shfl_xor_sync(0xffffffffu, sum1, 2);
    const float inv0 = 1.0f / sum0;
    const float inv1 = 1.0f / sum1;

    float o[8][4];
    #pragma unroll
    for (int nt = 0; nt < 8; nt++)
        #pragma unroll
        for (int e = 0; e < 4; e++) o[nt][e] = 0.f;

    const int vrow = ((lane >> 3) & 1) * 8 + (lane & 7);
    const int vcol = (lane >> 4) << 3;
    #pragma unroll
    for (int ks = 0; ks < 13; ks++) {
        unsigned ah0, ah1, ah2, ah3;
        if (ks < 12) {
            ah0 = pack_hi_h(s[2*ks][0],   s[2*ks][1]);   ah1 = pack_hi_h(s[2*ks][2],   s[2*ks][3]);
            ah2 = pack_hi_h(s[2*ks+1][0], s[2*ks+1][1]); ah3 = pack_hi_h(s[2*ks+1][2], s[2*ks+1][3]);
        } else {
            ah0 = pack_hi_h(s[24][0], s[24][1]); ah1 = pack_hi_h(s[24][2], s[24][3]);
            ah2 = 0u; ah3 = 0u;
        }
        const int k0 = ks * 16;
        #pragma unroll
        for (int np = 0; np < 4; np++) {
            const unsigned off = (unsigned)(((k0 + vrow) * ATT_LD + np * 16 + vcol) * 2);
            unsigned vh0, vh1, vh2, vh3;
            ldsm_x4t(vh0, vh1, vh2, vh3, uVH + off);
            mma16816h(o[2 * np],     ah0, ah1, ah2, ah3, vh0, vh1);
            mma16816h(o[2 * np + 1], ah0, ah1, ah2, ah3, vh2, vh3);
        }
    }

    const int r0 = m0 + (lane >> 2);
    const int r1 = r0 + 8;
    const int cb = h * DH + ((lane & 3) << 1);
    if (r0 < NT) {
        const size_t ob = (((size_t)b * NT + r0) * CC + cb) >> 1;
        #pragma unroll
        for (int nt = 0; nt < 8; nt++) {
            __half2 h2;
            h2.x = __float2half_rn(o[nt][0] * inv0);
            h2.y = __float2half_rn(o[nt][1] * inv0);
            reinterpret_cast<__half2*>(outh)[ob + nt * 4] = h2;
        }
    }
    if (r1 < NT) {
        const size_t ob = (((size_t)b * NT + r1) * CC + cb) >> 1;
        #pragma unroll
        for (int nt = 0; nt < 8; nt++) {
            __half2 h2;
            h2.x = __float2half_rn(o[nt][2] * inv1);
            h2.y = __float2half_rn(o[nt][3] * inv1);
            reinterpret_cast<__half2*>(outh)[ob + nt * 4] = h2;
        }
    }
}

// ---------------- depthwise 3x3 conv on V (tokens 1:), residual add ----------------
__global__ __launch_bounds__(256)
void dwconv_kernel(const __half* __restrict__ vh,
                   const float* __restrict__ wgt, const float* __restrict__ bias,
                   __half* __restrict__ ah)
{
    const int idx = blockIdx.x * 256 + threadIdx.x;
    const int c  = idx % CC;
    const int sp = (idx / CC) % (GRID * GRID);
    const int b  = idx / (CC * GRID * GRID);
    const int y = sp / GRID, x = sp - y * GRID;
    const int hh = c >> 6, d = c & 63;

    const size_t vbase = ((size_t)(b * HH + hh) * NT) * DH + d;
    float s = bias[c];
    #pragma unroll
    for (int ky = 0; ky < 3; ky++) {
        const int yy = y + ky - 1;
        if (yy < 0 || yy >= GRID) continue;
        #pragma unroll
        for (int kx = 0; kx < 3; kx++) {
            const int xx = x + kx - 1;
            if (xx < 0 || xx >= GRID) continue;
            const int t = 1 + yy * GRID + xx;
            s = fmaf(__half2float(vh[vbase + (size_t)t * DH]), wgt[c * 9 + ky * 3 + kx], s);
        }
    }
    const size_t oidx = ((size_t)b * NT + 1 + sp) * CC + c;
    ah[oidx] = __float2half_rn(__half2float(ah[oidx]) + s);
}

// ---------------- launch ----------------
extern "C" void kernel_launch(void* const* d_in, const int* in_sizes, int n_in,
                              void* d_out, int out_size)
{
    const float* x      = (const float*)d_in[0];
    const float* W_qkv  = (const float*)d_in[1];
    const float* b_qkv  = (const float*)d_in[2];
    const float* W_proj = (const float*)d_in[3];
    const float* b_proj = (const float*)d_in[4];
    const float* dwc_w  = (const float*)d_in[5];
    const float* dwc_b  = (const float*)d_in[6];
    float* out = (float*)d_out;

    __half *qh, *ql, *kh, *vh, *ah, *xh, *wqh, *wph;
    cudaGetSymbolAddress((void**)&qh,  g_qh);
    cudaGetSymbolAddress((void**)&ql,  g_ql);
    cudaGetSymbolAddress((void**)&kh,  g_kh);
    cudaGetSymbolAddress((void**)&vh,  g_vh);
    cudaGetSymbolAddress((void**)&ah,  g_ah);
    cudaGetSymbolAddress((void**)&xh,  g_xh);
    cudaGetSymbolAddress((void**)&wqh, g_wqh);
    cudaGetSymbolAddress((void**)&wph, g_wph);

    // 0) convert all fp32 operands to fp16
    cvt_hi_kernel<<<(M_ROWS * CC / 4) / 256, 256>>>(x, xh);
    cvt_hi_kernel<<<(CC * 3 * CC / 4) / 256, 256>>>(W_qkv, wqh);
    cvt_hi_kernel<<<(CC * CC / 4) / 256, 256>>>(W_proj, wph);

    // 1) qkv projection (fp16, K-stage 64) -> q(scaled, hi/lo), k, v in (B,H,N,D)
    {
        cudaFuncSetAttribute(mma_gemm_h<1>, cudaFuncAttributeMaxDynamicSharedMemorySize,
                             G2_TOTAL);
        dim3 grid(3 * CC / 128, M_ROWS / 128);
        mma_gemm_h<1><<<grid, 256, G2_TOTAL>>>(xh, wqh, b_qkv, nullptr,
                                               qh, ql, kh, vh,
                                               M_ROWS, 3 * CC, CC);
    }

    // 2) fp16 tensor-core attention -> ah
    {
        const int smem_bytes = 4 * ATT_ELEMS * (int)sizeof(__half);  // 119808
        cudaFuncSetAttribute(attn_mma_kernel, cudaFuncAttributeMaxDynamicSharedMemorySize,
                             smem_bytes);
        attn_mma_kernel<<<Bv * HH, 416, smem_bytes>>>(qh, ql, kh, vh, ah);
    }

    // 3) depthwise conv + residual add into ah rows 1:
    {
        const int total = Bv * GRID * GRID * CC;
        dwconv_kernel<<<total / 256, 256>>>(vh, dwc_w, dwc_b, ah);
    }

    // 4) output projection (fp16, K-stage 64)
    {
        cudaFuncSetAttribute(mma_gemm_h<0>, cudaFuncAttributeMaxDynamicSharedMemorySize,
                             G2_TOTAL);
        dim3 grid(CC / 128, M_ROWS / 128);
        mma_gemm_h<0><<<grid, 256, G2_TOTAL>>>(ah, wph, b_proj, out,
                                               nullptr, nullptr, nullptr, nullptr,
                                               M_ROWS, CC, CC);
    }
}

// round 15
// speedup vs baseline: 2.8920x; 1.1929x over previous
#include <cuda_runtime.h>
#include <cuda_fp16.h>
#include <math.h>

#define Bv 256
#define NT 197
#define CC 768
#define HH 12
#define DH 64
#define GRID 14
#define M_ROWS (Bv * NT)          // 50432 = 394*128

// ---------------- scratch ----------------
__device__ __half g_qh[(size_t)Bv * HH * NT * DH];
__device__ __half g_ql[(size_t)Bv * HH * NT * DH];
__device__ __half g_kh[(size_t)Bv * HH * NT * DH];
__device__ __half g_vh[(size_t)Bv * HH * NT * DH];
__device__ __half g_ah[(size_t)M_ROWS * CC];
__device__ __half g_xh[(size_t)M_ROWS * CC];
__device__ __half g_wqh[(size_t)CC * 3 * CC];
__device__ __half g_wph[(size_t)CC * CC];

// ---------------- helpers ----------------
__device__ __forceinline__ unsigned smem_u32(const void* p) {
    return (unsigned)__cvta_generic_to_shared(p);
}
__device__ __forceinline__ void cp_async16_u(unsigned s, const void* g) {
    asm volatile("cp.async.cg.shared.global [%0], [%1], 16;\n" :: "r"(s), "l"(g));
}
__device__ __forceinline__ void ldsm_x4(unsigned& r0, unsigned& r1, unsigned& r2, unsigned& r3,
                                        unsigned addr) {
    asm volatile("ldmatrix.sync.aligned.m8n8.x4.shared.b16 {%0,%1,%2,%3}, [%4];\n"
                 : "=r"(r0), "=r"(r1), "=r"(r2), "=r"(r3) : "r"(addr));
}
__device__ __forceinline__ void ldsm_x4t(unsigned& r0, unsigned& r1, unsigned& r2, unsigned& r3,
                                         unsigned addr) {
    asm volatile("ldmatrix.sync.aligned.m8n8.x4.trans.shared.b16 {%0,%1,%2,%3}, [%4];\n"
                 : "=r"(r0), "=r"(r1), "=r"(r2), "=r"(r3) : "r"(addr));
}
__device__ __forceinline__ void mma16816h(float* c, unsigned a0, unsigned a1, unsigned a2,
                                          unsigned a3, unsigned b0, unsigned b1) {
    asm volatile("mma.sync.aligned.m16n8k16.row.col.f32.f16.f16.f32 "
                 "{%0,%1,%2,%3}, {%4,%5,%6,%7}, {%8,%9}, {%0,%1,%2,%3};\n"
                 : "+f"(c[0]), "+f"(c[1]), "+f"(c[2]), "+f"(c[3])
                 : "r"(a0), "r"(a1), "r"(a2), "r"(a3), "r"(b0), "r"(b1));
}
__device__ __forceinline__ void split2h(float x, float y, __half2& h, __half2& l) {
    h.x = __float2half_rn(x); l.x = __float2half_rn(x - __half2float(h.x));
    h.y = __float2half_rn(y); l.y = __float2half_rn(y - __half2float(h.y));
}
__device__ __forceinline__ unsigned pack_hi_h(float x, float y) {
    __half2 t; t.x = __float2half_rn(x); t.y = __float2half_rn(y);
    return *reinterpret_cast<unsigned*>(&t);
}

// ---------------- convert kernel (fp32 -> fp16) ----------------
__global__ __launch_bounds__(256)
void cvt_hi_kernel(const float* __restrict__ src, __half* __restrict__ hi)
{
    const int i = blockIdx.x * 256 + threadIdx.x;
    float4 v = reinterpret_cast<const float4*>(src)[i];
    __half2 h0, h1;
    h0.x = __float2half_rn(v.x); h0.y = __float2half_rn(v.y);
    h1.x = __float2half_rn(v.z); h1.y = __float2half_rn(v.w);
    reinterpret_cast<__half2*>(hi + (size_t)i * 4)[0] = h0;
    reinterpret_cast<__half2*>(hi + (size_t)i * 4)[1] = h1;
}

// ---------------- fp16 GEMM: 128x128x64 CTA, 256 threads, 2-stage ----------------
#define LDA2 72   // 64 + 8 pad (fp16)
#define LDB2 136  // 128 + 8 pad
#define G2_A   (128 * LDA2 * 2)               // 18432 B
#define G2_B   (64 * LDB2 * 2)                // 17408 B
#define G2_STAGE (G2_A + G2_B)                // 35840 B
#define G2_TOTAL (2 * G2_STAGE)               // 71680 B

template<int MODE>
__global__ __launch_bounds__(256, 2)
void mma_gemm_h(const __half* __restrict__ Agh,
                const __half* __restrict__ Bgh,
                const float* __restrict__ bias, float* __restrict__ C,
                __half* __restrict__ Qh, __half* __restrict__ Ql,
                __half* __restrict__ Kh, __half* __restrict__ Vh,
                int M, int N, int K)
{
    extern __shared__ char gsm[];
    const unsigned smBase = smem_u32(gsm);

    const int tid  = threadIdx.x;
    const int brow = blockIdx.y;
    const int bcol = blockIdx.x;
    const int lane = tid & 31;
    const int wid  = tid >> 5;
    const int wm = (wid & 1) * 64;
    const int wn = (wid >> 1) * 32;
    const int aRowBase = brow * 128;
    const int bColBase = bcol * 128;

    float acc[4][4][4];
    #pragma unroll
    for (int mt = 0; mt < 4; mt++)
        #pragma unroll
        for (int nt = 0; nt < 4; nt++)
            #pragma unroll
            for (int e = 0; e < 4; e++) acc[mt][nt][e] = 0.f;

    const int aRowLane = lane & 15;
    const int aColLane = (lane >> 4) << 3;
    const int bRow16  = ((lane >> 3) & 1) * 8 + (lane & 7);
    const int bColSel = (lane >> 4) << 3;

    auto issue = [&](int k0, int st) {
        const unsigned stBase = smBase + st * G2_STAGE;
        #pragma unroll
        for (int c = 0; c < 4; c++) {
            const int chunk = tid + c * 256;          // 0..1023
            const int arow = chunk >> 3;
            const int acol = (chunk & 7) << 3;
            const size_t aoff = (size_t)(aRowBase + arow) * K + k0 + acol;
            cp_async16_u(stBase + (arow * LDA2 + acol) * 2, Agh + aoff);
        }
        #pragma unroll
        for (int c = 0; c < 4; c++) {
            const int chunk = tid + c * 256;          // 0..1023
            const int brw = chunk >> 4;
            const int bcl = (chunk & 15) << 3;
            const size_t boff = (size_t)(k0 + brw) * N + bColBase + bcl;
            cp_async16_u(stBase + G2_A + (brw * LDB2 + bcl) * 2, Bgh + boff);
        }
        asm volatile("cp.async.commit_group;\n");
    };

    const int NIT = K >> 6;   // K-stage 64
    issue(0, 0);

    for (int it = 0; it < NIT; ++it) {
        if (it + 1 < NIT) {
            issue((it + 1) << 6, (it + 1) & 1);
            asm volatile("cp.async.wait_group 1;\n");
        } else {
            asm volatile("cp.async.wait_group 0;\n");
        }
        __syncthreads();

        const unsigned stBase = smBase + (it & 1) * G2_STAGE;
        const unsigned aBaseH = stBase;
        const unsigned bBaseH = stBase + G2_A;

        #pragma unroll
        for (int ks = 0; ks < 4; ks++) {
            unsigned bhf[4][2];
            #pragma unroll
            for (int np = 0; np < 2; np++) {
                const unsigned boff = ((ks * 16 + bRow16) * LDB2 + wn + np * 16 + bColSel) * 2;
                ldsm_x4t(bhf[2 * np][0], bhf[2 * np][1],
                         bhf[2 * np + 1][0], bhf[2 * np + 1][1], bBaseH + boff);
            }
            #pragma unroll
            for (int mt = 0; mt < 4; mt++) {
                const unsigned aoff = ((wm + mt * 16 + aRowLane) * LDA2 + ks * 16 + aColLane) * 2;
                unsigned ah0, ah1, ah2, ah3;
                ldsm_x4(ah0, ah1, ah2, ah3, aBaseH + aoff);
                #pragma unroll
                for (int nt = 0; nt < 4; nt++) {
                    mma16816h(acc[mt][nt], ah0, ah1, ah2, ah3, bhf[nt][0], bhf[nt][1]);
                }
            }
        }
        __syncthreads();
    }

    const int trow = lane >> 2;
    const int tcol = (lane & 3) << 1;
    #pragma unroll
    for (int mt = 0; mt < 4; mt++) {
        #pragma unroll
        for (int nt = 0; nt < 4; nt++) {
            const int gc = bColBase + wn + nt * 8 + tcol;
            const float bia0 = bias[gc];
            const float bia1 = bias[gc + 1];
            #pragma unroll
            for (int half_ = 0; half_ < 2; half_++) {
                const int gr = aRowBase + wm + mt * 16 + trow + half_ * 8;
                float2 val;
                val.x = acc[mt][nt][half_ * 2 + 0] + bia0;
                val.y = acc[mt][nt][half_ * 2 + 1] + bia1;
                if (MODE == 0) {
                    *(float2*)&C[(size_t)gr * N + gc] = val;
                } else {
                    const int b_ = gr / NT;
                    const int t  = gr - b_ * NT;
                    const int s  = gc / CC;
                    const int r  = gc - s * CC;
                    const int hh = r >> 6;
                    const int d  = r & 63;
                    const size_t idx2 = (((size_t)((b_ * HH + hh) * NT + t)) * DH + d) >> 1;
                    if (s == 0) {
                        val.x *= 0.125f; val.y *= 0.125f;
                        __half2 h2, l2;
                        split2h(val.x, val.y, h2, l2);
                        reinterpret_cast<__half2*>(Qh)[idx2] = h2;
                        reinterpret_cast<__half2*>(Ql)[idx2] = l2;
                    } else {
                        __half2 h2;
                        h2.x = __float2half_rn(val.x);
                        h2.y = __float2half_rn(val.y);
                        reinterpret_cast<__half2*>((s == 1) ? Kh : Vh)[idx2] = h2;
                    }
                }
            }
        }
    }
}

// ---------------- fp16 attention + fused depthwise conv: one CTA per (b,h), 416 threads ----------------
#define ATT_ROWS 208
#define ATT_LD 72
#define ATT_ELEMS (ATT_ROWS * ATT_LD)   // 14976

__global__ __launch_bounds__(416, 1)
void attn_mma_kernel(const __half* __restrict__ qh, const __half* __restrict__ ql,
                     const __half* __restrict__ kh, const __half* __restrict__ vh,
                     const float* __restrict__ dwc_w, const float* __restrict__ dwc_b,
                     __half* __restrict__ outh)
{
    extern __shared__ __half sm[];
    __half* smQH = sm;
    __half* smQL = sm + ATT_ELEMS;
    __half* smKH = sm + 2 * ATT_ELEMS;
    __half* smVH = sm + 3 * ATT_ELEMS;

    const int bh = blockIdx.x;
    const int b  = bh / HH;
    const int h  = bh - b * HH;
    const size_t base = (size_t)bh * NT * DH;
    const int tid  = threadIdx.x;
    const int lane = tid & 31;
    const int wid  = tid >> 5;     // 0..12

    const unsigned uQH = smem_u32(smQH);
    const unsigned uQL = smem_u32(smQL);
    const unsigned uKH = smem_u32(smKH);
    const unsigned uVH = smem_u32(smVH);

    for (int i = tid; i < NT * 8; i += 416) {      // 197 rows x 8 chunks
        const int row = i >> 3;
        const int j = i & 7;
        const unsigned doff = (unsigned)((row * ATT_LD + j * 8) * 2);
        const size_t soff = base + (size_t)row * DH + j * 8;
        cp_async16_u(uQH + doff, qh + soff);
        cp_async16_u(uQL + doff, ql + soff);
        cp_async16_u(uKH + doff, kh + soff);
        cp_async16_u(uVH + doff, vh + soff);
    }
    const float4 z4 = make_float4(0.f, 0.f, 0.f, 0.f);
    for (int i = tid; i < 11 * 8; i += 416) {
        const int row = NT + (i >> 3);
        const int j = i & 7;
        const int off = row * ATT_LD + j * 8;
        *(float4*)&smQH[off] = z4; *(float4*)&smQL[off] = z4;
        *(float4*)&smKH[off] = z4; *(float4*)&smVH[off] = z4;
    }
    asm volatile("cp.async.commit_group;\n");
    asm volatile("cp.async.wait_group 0;\n");
    __syncthreads();

    const int m0 = wid * 16;

    unsigned qf[4][4], qg[4][4];
    {
        const int r  = m0 + (lane & 15);
        const int cb = (lane >> 4) << 3;
        #pragma unroll
        for (int ks = 0; ks < 4; ks++) {
            const unsigned off = (unsigned)((r * ATT_LD + ks * 16 + cb) * 2);
            ldsm_x4(qf[ks][0], qf[ks][1], qf[ks][2], qf[ks][3], uQH + off);
            ldsm_x4(qg[ks][0], qg[ks][1], qg[ks][2], qg[ks][3], uQL + off);
        }
    }

    float s[25][4];
    #pragma unroll
    for (int nt = 0; nt < 25; nt++)
        #pragma unroll
        for (int e = 0; e < 4; e++) s[nt][e] = 0.f;

    const int krow = lane & 7;
    const int kcol = ((lane >> 3) & 3) << 3;
    #pragma unroll
    for (int nt = 0; nt < 25; nt++) {
        const int n0 = nt * 8;
        unsigned khf[4][2];
        {
            const unsigned o1 = (unsigned)(((n0 + krow) * ATT_LD + kcol) * 2);
            unsigned r0, r1, r2, r3;
            ldsm_x4(r0, r1, r2, r3, uKH + o1);
            khf[0][0] = r0; khf[0][1] = r1; khf[1][0] = r2; khf[1][1] = r3;
            ldsm_x4(r0, r1, r2, r3, uKH + o1 + 64);
            khf[2][0] = r0; khf[2][1] = r1; khf[3][0] = r2; khf[3][1] = r3;
        }
        #pragma unroll
        for (int ks = 0; ks < 4; ks++) {
            mma16816h(s[nt], qf[ks][0], qf[ks][1], qf[ks][2], qf[ks][3], khf[ks][0], khf[ks][1]);
            mma16816h(s[nt], qg[ks][0], qg[ks][1], qg[ks][2], qg[ks][3], khf[ks][0], khf[ks][1]);
        }
    }

    {
        const int col0 = 192 + ((lane & 3) << 1);
        if (col0     >= NT) { s[24][0] = -1e30f; s[24][2] = -1e30f; }
        if (col0 + 1 >= NT) { s[24][1] = -1e30f; s[24][3] = -1e30f; }
    }
    float mx0 = -1e30f, mx1 = -1e30f;
    #pragma unroll
    for (int nt = 0; nt < 25; nt++) {
        mx0 = fmaxf(mx0, fmaxf(s[nt][0], s[nt][1]));
        mx1 = fmaxf(mx1, fmaxf(s[nt][2], s[nt][3]));
    }
    mx0 = fmaxf(mx0, __shfl_xor_sync(0xffffffffu, mx0, 1));
    mx0 = fmaxf(mx0, __shfl_xor_sync(0xffffffffu, mx0, 2));
    mx1 = fmaxf(mx1, __shfl_xor_sync(0xffffffffu, mx1, 1));
    mx1 = fmaxf(mx1, __shfl_xor_sync(0xffffffffu, mx1, 2));

    float sum0 = 0.f, sum1 = 0.f;
    #pragma unroll
    for (int nt = 0; nt < 25; nt++) {
        const float e0 = __expf(s[nt][0] - mx0);
        const float e1 = __expf(s[nt][1] - mx0);
        const float e2 = __expf(s[nt][2] - mx1);
        const float e3 = __expf(s[nt][3] - mx1);
        s[nt][0] = e0; s[nt][1] = e1; s[nt][2] = e2; s[nt][3] = e3;
        sum0 += e0 + e1; sum1 += e2 + e3;
    }
    sum0 += __shfl_xor_sync(0xffffffffu, sum0, 1);
    sum0 += __shfl_xor_sync(0xffffffffu, sum0, 2);
    sum1 += __shfl_xor_sync(0xffffffffu, sum1, 1);
    sum1 += __shfl_xor_sync(0xffffffffu, sum1, 2);
    const float inv0 = 1.0f / sum0;
    const float inv1 = 1.0f / sum1;

    float o[8][4];
    #pragma unroll
    for (int nt = 0; nt < 8; nt++)
        #pragma unroll
        for (int e = 0; e < 4; e++) o[nt][e] = 0.f;

    const int vrow = ((lane >> 3) & 1) * 8 + (lane & 7);
    const int vcol = (lane >> 4) << 3;
    #pragma unroll
    for (int ks = 0; ks < 13; ks++) {
        unsigned ah0, ah1, ah2, ah3;
        if (ks < 12) {
            ah0 = pack_hi_h(s[2*ks][0],   s[2*ks][1]);   ah1 = pack_hi_h(s[2*ks][2],   s[2*ks][3]);
            ah2 = pack_hi_h(s[2*ks+1][0], s[2*ks+1][1]); ah3 = pack_hi_h(s[2*ks+1][2], s[2*ks+1][3]);
        } else {
            ah0 = pack_hi_h(s[24][0], s[24][1]); ah1 = pack_hi_h(s[24][2], s[24][3]);
            ah2 = 0u; ah3 = 0u;
        }
        const int k0 = ks * 16;
        #pragma unroll
        for (int np = 0; np < 4; np++) {
            const unsigned off = (unsigned)(((k0 + vrow) * ATT_LD + np * 16 + vcol) * 2);
            unsigned vh0, vh1, vh2, vh3;
            ldsm_x4t(vh0, vh1, vh2, vh3, uVH + off);
            mma16816h(o[2 * np],     ah0, ah1, ah2, ah3, vh0, vh1);
            mma16816h(o[2 * np + 1], ah0, ah1, ah2, ah3, vh2, vh3);
        }
    }

    // ---- fused depthwise conv + store ----
    const int r0 = m0 + (lane >> 2);
    const int r1 = r0 + 8;
    const int tc2 = (lane & 3) << 1;
    const bool c0v = (r0 >= 1 && r0 < NT);
    const bool c1v = (r1 >= 1 && r1 < NT);
    int y0 = 0, x0 = 0, y1 = 0, x1 = 0;
    if (c0v) { const int sp = r0 - 1; y0 = sp / GRID; x0 = sp - y0 * GRID; }
    if (c1v) { const int sp = r1 - 1; y1 = sp / GRID; x1 = sp - y1 * GRID; }

    #pragma unroll
    for (int nt = 0; nt < 8; nt++) {
        const int d0 = tc2 + nt * 8;           // channel within head (even)
        const int c  = h * DH + d0;            // global channel
        float cv00 = 0.f, cv01 = 0.f, cv10 = 0.f, cv11 = 0.f;
        if (c0v || c1v) {
            #pragma unroll
            for (int ky = 0; ky < 3; ky++) {
                #pragma unroll
                for (int kx = 0; kx < 3; kx++) {
                    const float w0 = __ldg(&dwc_w[(size_t)c * 9 + ky * 3 + kx]);
                    const float w1 = __ldg(&dwc_w[(size_t)(c + 1) * 9 + ky * 3 + kx]);
                    if (c0v) {
                        const int yy = y0 + ky - 1, xx = x0 + kx - 1;
                        if (yy >= 0 && yy < GRID && xx >= 0 && xx < GRID) {
                            const int t = 1 + yy * GRID + xx;
                            const __half2 v2 = *reinterpret_cast<const __half2*>(&smVH[t * ATT_LD + d0]);
                            cv00 = fmaf(__half2float(v2.x), w0, cv00);
                            cv01 = fmaf(__half2float(v2.y), w1, cv01);
                        }
                    }
                    if (c1v) {
                        const int yy = y1 + ky - 1, xx = x1 + kx - 1;
                        if (yy >= 0 && yy < GRID && xx >= 0 && xx < GRID) {
                            const int t = 1 + yy * GRID + xx;
                            const __half2 v2 = *reinterpret_cast<const __half2*>(&smVH[t * ATT_LD + d0]);
                            cv10 = fmaf(__half2float(v2.x), w0, cv10);
                            cv11 = fmaf(__half2float(v2.y), w1, cv11);
                        }
                    }
                }
            }
            const float bb0 = __ldg(&dwc_b[c]);
            const float bb1 = __ldg(&dwc_b[c + 1]);
            if (c0v) { cv00 += bb0; cv01 += bb1; }
            if (c1v) { cv10 += bb0; cv11 += bb1; }
        }
        if (r0 < NT) {
            __half2 h2;
            h2.x = __float2half_rn(o[nt][0] * inv0 + cv00);
            h2.y = __float2half_rn(o[nt][1] * inv0 + cv01);
            *reinterpret_cast<__half2*>(&outh[((size_t)b * NT + r0) * CC + c]) = h2;
        }
        if (r1 < NT) {
            __half2 h2;
            h2.x = __float2half_rn(o[nt][2] * inv1 + cv10);
            h2.y = __float2half_rn(o[nt][3] * inv1 + cv11);
            *reinterpret_cast<__half2*>(&outh[((size_t)b * NT + r1) * CC + c]) = h2;
        }
    }
}

// ---------------- launch ----------------
extern "C" void kernel_launch(void* const* d_in, const int* in_sizes, int n_in,
                              void* d_out, int out_size)
{
    const float* x      = (const float*)d_in[0];
    const float* W_qkv  = (const float*)d_in[1];
    const float* b_qkv  = (const float*)d_in[2];
    const float* W_proj = (const float*)d_in[3];
    const float* b_proj = (const float*)d_in[4];
    const float* dwc_w  = (const float*)d_in[5];
    const float* dwc_b  = (const float*)d_in[6];
    float* out = (float*)d_out;

    __half *qh, *ql, *kh, *vh, *ah, *xh, *wqh, *wph;
    cudaGetSymbolAddress((void**)&qh,  g_qh);
    cudaGetSymbolAddress((void**)&ql,  g_ql);
    cudaGetSymbolAddress((void**)&kh,  g_kh);
    cudaGetSymbolAddress((void**)&vh,  g_vh);
    cudaGetSymbolAddress((void**)&ah,  g_ah);
    cudaGetSymbolAddress((void**)&xh,  g_xh);
    cudaGetSymbolAddress((void**)&wqh, g_wqh);
    cudaGetSymbolAddress((void**)&wph, g_wph);

    // 0) convert all fp32 operands to fp16
    cvt_hi_kernel<<<(M_ROWS * CC / 4) / 256, 256>>>(x, xh);
    cvt_hi_kernel<<<(CC * 3 * CC / 4) / 256, 256>>>(W_qkv, wqh);
    cvt_hi_kernel<<<(CC * CC / 4) / 256, 256>>>(W_proj, wph);

    // 1) qkv projection (fp16, K-stage 64) -> q(scaled, hi/lo), k, v in (B,H,N,D)
    {
        cudaFuncSetAttribute(mma_gemm_h<1>, cudaFuncAttributeMaxDynamicSharedMemorySize,
                             G2_TOTAL);
        dim3 grid(3 * CC / 128, M_ROWS / 128);
        mma_gemm_h<1><<<grid, 256, G2_TOTAL>>>(xh, wqh, b_qkv, nullptr,
                                               qh, ql, kh, vh,
                                               M_ROWS, 3 * CC, CC);
    }

    // 2) fp16 attention + fused depthwise conv -> ah
    {
        const int smem_bytes = 4 * ATT_ELEMS * (int)sizeof(__half);  // 119808
        cudaFuncSetAttribute(attn_mma_kernel, cudaFuncAttributeMaxDynamicSharedMemorySize,
                             smem_bytes);
        attn_mma_kernel<<<Bv * HH, 416, smem_bytes>>>(qh, ql, kh, vh, dwc_w, dwc_b, ah);
    }

    // 3) output projection (fp16, K-stage 64)
    {
        cudaFuncSetAttribute(mma_gemm_h<0>, cudaFuncAttributeMaxDynamicSharedMemorySize,
                             G2_TOTAL);
        dim3 grid(CC / 128, M_ROWS / 128);
        mma_gemm_h<0><<<grid, 256, G2_TOTAL>>>(ah, wph, b_proj, out,
                                               nullptr, nullptr, nullptr, nullptr,
                                               M_ROWS, CC, CC);
    }
}